// round 15
// baseline (speedup 1.0000x reference)
#include <cuda_runtime.h>
#include <cstdint>
#include <cstddef>

#define BB 64
#define TT 2048
#define DD 256
#define HH 512
#define GCN 2048   /* 4*HH gate columns: [j|i|f|o] */
#define RBLOCKS 128

typedef unsigned long long ull;

// ---------------- scratch (device globals: allocation-free rule) ----------------
__device__ float g_xproj[(size_t)TT * GCN * BB];   // [t][gc][b]  (1 GiB)
__device__ float g_hs[(size_t)TT * BB * HH];       // [t][b][h]   (256 MiB)
__device__ unsigned g_cnt;                         // arrival counter (zeroed per launch)

__device__ __forceinline__ float fsigmoid_(float x) {
    return 1.0f / (1.0f + __expf(-x));
}
__device__ __forceinline__ float ftanh_(float x) {
    float e = __expf(2.0f * x);
    return 1.0f - 2.0f / (e + 1.0f);
}

// ---- packed f32x2 helpers (FFMA2 path: only reachable via PTX) ----
__device__ __forceinline__ ull bcast2(float v) {
    ull r;
    asm("mov.b64 %0, {%1, %1};" : "=l"(r) : "r"(__float_as_uint(v)));
    return r;
}
__device__ __forceinline__ void fma2(ull& d, ull a, ull b) {
    asm("fma.rn.f32x2 %0, %1, %2, %0;" : "+l"(d) : "l"(a), "l"(b));
}
__device__ __forceinline__ void add2(ull& d, ull a) {
    asm("add.rn.f32x2 %0, %0, %1;" : "+l"(d) : "l"(a));
}
__device__ __forceinline__ float2 unpack2(ull v) {
    unsigned lo, hi;
    asm("mov.b64 {%0, %1}, %2;" : "=r"(lo), "=r"(hi) : "l"(v));
    return make_float2(__uint_as_float(lo), __uint_as_float(hi));
}

// ---- cp.async helpers ----
__device__ __forceinline__ void cp16(void* dst_smem, const void* src_gmem) {
    unsigned d = (unsigned)__cvta_generic_to_shared(dst_smem);
    asm volatile("cp.async.cg.shared.global [%0], [%1], 16;\n" :: "r"(d), "l"(src_gmem));
}
__device__ __forceinline__ void cp_commit() {
    asm volatile("cp.async.commit_group;\n");
}
template <int N> __device__ __forceinline__ void cp_wait() {
    asm volatile("cp.async.wait_group %0;\n" :: "n"(N));
}

// =====================================================================
// Kernel 0: zero the barrier counter
// =====================================================================
__global__ void init_kernel() {
    g_cnt = 0u;
}

// =====================================================================
// Kernel 1: input projections (double-buffered SGEMM, f32x2 math)
// =====================================================================
__global__ void __launch_bounds__(256) proj_kernel(
    const float* __restrict__ x,
    const float* __restrict__ Wj, const float* __restrict__ Wi,
    const float* __restrict__ Wf, const float* __restrict__ Wo,
    const float* __restrict__ bj, const float* __restrict__ bi,
    const float* __restrict__ bf, const float* __restrict__ bo)
{
    extern __shared__ float sm[];
    float* Wsm = sm;                 // [2][32 kk][128 gc]
    float* Xsm = sm + 2 * 32 * 128;  // [2][64 b][40]

    const int t   = blockIdx.y;
    const int gc0 = blockIdx.x * 128;
    const int g   = gc0 >> 9;
    const int hq0 = gc0 & 511;
    const float* W  = (g == 0) ? Wj : (g == 1) ? Wi : (g == 2) ? Wf : Wo;
    const float* bv = (g == 0) ? bj : (g == 1) ? bi : (g == 2) ? bf : bo;
    const int tid = threadIdx.x;
    const int tb = tid >> 4;
    const int tc = tid & 15;

    ull A[4][4];
#pragma unroll
    for (int j = 0; j < 4; j++)
#pragma unroll
        for (int p = 0; p < 4; p++) A[j][p] = 0ull;

    auto prefetch = [&](int kc, int buf) {
        const float* Wp = W + (size_t)(kc * 32) * HH + hq0;
        float* wd = Wsm + buf * (32 * 128);
#pragma unroll
        for (int r = 0; r < 4; r++) {
            int idx = r * 256 + tid;
            int kk = idx >> 5, c4 = idx & 31;
            cp16(wd + kk * 128 + c4 * 4, Wp + (size_t)kk * HH + c4 * 4);
        }
        float* xd = Xsm + buf * (64 * 40);
#pragma unroll
        for (int r = 0; r < 2; r++) {
            int idx = r * 256 + tid;
            int bb = idx >> 3, k4 = idx & 7;
            cp16(xd + bb * 40 + k4 * 4,
                 x + ((size_t)bb * TT + t) * DD + kc * 32 + k4 * 4);
        }
    };

    prefetch(0, 0);
    cp_commit();

    for (int kc = 0; kc < 8; kc++) {
        int buf = kc & 1;
        if (kc < 7) prefetch(kc + 1, buf ^ 1);
        cp_commit();
        cp_wait<1>();
        __syncthreads();

        const float4* Wb4 = (const float4*)(Wsm + buf * (32 * 128));
        const float*  Xb  = Xsm + buf * (64 * 40);
#pragma unroll
        for (int kk4 = 0; kk4 < 8; kk4++) {
            float4 xq[4];
#pragma unroll
            for (int j = 0; j < 4; j++)
                xq[j] = *(const float4*)(Xb + (tb * 4 + j) * 40 + kk4 * 4);
#pragma unroll
            for (int q = 0; q < 4; q++) {
                int kk = kk4 * 4 + q;
                ulonglong2 w0 = *(const ulonglong2*)(Wb4 + kk * 32 + tc);
                ulonglong2 w1 = *(const ulonglong2*)(Wb4 + kk * 32 + 16 + tc);
#pragma unroll
                for (int j = 0; j < 4; j++) {
                    float xs = ((const float*)&xq[j])[q];
                    ull hj = bcast2(xs);
                    fma2(A[j][0], hj, w0.x);
                    fma2(A[j][1], hj, w0.y);
                    fma2(A[j][2], hj, w1.x);
                    fma2(A[j][3], hj, w1.y);
                }
            }
        }
        __syncthreads();
    }

    float acc[4][8];
#pragma unroll
    for (int j = 0; j < 4; j++)
#pragma unroll
        for (int p = 0; p < 4; p++) {
            float2 v = unpack2(A[j][p]);
            acc[j][p * 2 + 0] = v.x;
            acc[j][p * 2 + 1] = v.y;
        }
#pragma unroll
    for (int i4 = 0; i4 < 2; i4++) {
#pragma unroll
        for (int q = 0; q < 4; q++) {
            int c = i4 * 64 + tc * 4 + q;
            float bb = bv[hq0 + c];
            float4 v = make_float4(acc[0][i4 * 4 + q] + bb, acc[1][i4 * 4 + q] + bb,
                                   acc[2][i4 * 4 + q] + bb, acc[3][i4 * 4 + q] + bb);
            *(float4*)(g_xproj + ((size_t)t * GCN + gc0 + c) * BB + tb * 4) = v;
        }
    }
}

// =====================================================================
// Kernel 2: persistent recurrence. 128 blocks x 384 threads.
// Warps 0-3: stage h via cp.async (half0 group, half1 group per thread)
// — unchanged R7/R13 staging. Warps 4-11: compute, 2 warps per SMSP,
// 1 (b,hq) pair per lane, R13 software-pipelined inner loop (8 chains).
// Two pipelined warps per SMSP interleave: stalls in one are absorbed
// by the other. Barrier: proven red+single-line poll.
// =====================================================================
__global__ void __launch_bounds__(384) recur_kernel(
    const float* __restrict__ h0in, const float* __restrict__ c0in,
    const float* __restrict__ Uj, const float* __restrict__ Ui,
    const float* __restrict__ Uf, const float* __restrict__ Uo,
    float* __restrict__ dout)
{
    extern __shared__ float sm[];
    float* h_smf = sm;               // [64 b][512 k], xor-swizzled float4
    float* U_sm  = sm + 64 * 512;    // [128 k4][4 l][20]: [g][hk0..3] + 4 pad

    const int tid  = threadIdx.x;
    const int bidx = blockIdx.x;
    const int hq_base = bidx * 4;

    // U fill: U_sm[k4*80 + l*20 + g*4 + i] = U_g[(k4*4+i)][hq_base+l]
    for (int idx = tid; idx < 128 * 80; idx += 384) {
        int k4 = idx / 80;
        int r  = idx - k4 * 80;
        int l  = r / 20;
        int s  = r - l * 20;
        float v = 0.0f;
        if (s < 16) {
            int g = s >> 2, i = s & 3;
            const float* Up = (g == 0) ? Uj : (g == 1) ? Ui : (g == 2) ? Uf : Uo;
            v = Up[(size_t)(k4 * 4 + i) * HH + hq_base + l];
        }
        U_sm[idx] = v;
    }
    __syncthreads();

    const bool is_compute = (tid >= 128);
    // staging identity (warps 0-3): thread owns k4-pair (scol, scol+64)
    const int scol = tid & 63;
    const int sbb0 = (tid >> 6) * 32;       // 0 or 32 (within tid<128)
    // compute identity (warps 4-11): 1 (b,hq) pair per lane
    const int cwid = (tid - 128) >> 5;      // 0..7
    const int lane = tid & 31;
    const int l    = lane >> 3;             // hq lane 0..3
    const int bq   = lane & 7;
    const int B    = cwid * 8 + bq;         // 0..63
    const int hq   = hq_base + l;

    float4* h4 = (float4*)h_smf;
    const ulonglong2* h2 = (const ulonglong2*)h_smf;
    const float* Ub = U_sm + l * 20;

    float c = 0.f, hval = 0.f;
    if (is_compute) c = c0in[(size_t)B * HH + hq];

    // 8 chains: [gate] x {even,odd} hk partials
    ull Ae[4], Ao[4];

#define FMA8(HP, U0, U1, U2, U3)                                               \
        fma2(Ae[0], (HP).x, (U0).x); fma2(Ao[0], (HP).y, (U0).y);              \
        fma2(Ae[1], (HP).x, (U1).x); fma2(Ao[1], (HP).y, (U1).y);              \
        fma2(Ae[2], (HP).x, (U2).x); fma2(Ao[2], (HP).y, (U2).y);              \
        fma2(Ae[3], (HP).x, (U3).x); fma2(Ao[3], (HP).y, (U3).y);

#define PIPE_HALF(LO)                                                          \
        {                                                                      \
            ulonglong2 chp = h2[B * 128 + ((LO) ^ bq)];                        \
            const float* Uc = Ub + (LO) * 80;                                  \
            ulonglong2 cu0 = *(const ulonglong2*)(Uc + 0);                     \
            ulonglong2 cu1 = *(const ulonglong2*)(Uc + 4);                     \
            ulonglong2 cu2 = *(const ulonglong2*)(Uc + 8);                     \
            ulonglong2 cu3 = *(const ulonglong2*)(Uc + 12);                    \
            _Pragma("unroll 7")                                                \
            for (int k4 = (LO); k4 < (LO) + 63; k4++) {                        \
                ulonglong2 nhp = h2[B * 128 + ((k4 + 1) ^ bq)];                \
                const float* Un = Ub + (k4 + 1) * 80;                          \
                ulonglong2 nu0 = *(const ulonglong2*)(Un + 0);                 \
                ulonglong2 nu1 = *(const ulonglong2*)(Un + 4);                 \
                ulonglong2 nu2 = *(const ulonglong2*)(Un + 8);                 \
                ulonglong2 nu3 = *(const ulonglong2*)(Un + 12);                \
                FMA8(chp, cu0, cu1, cu2, cu3)                                  \
                chp = nhp;                                                     \
                cu0 = nu0; cu1 = nu1; cu2 = nu2; cu3 = nu3;                    \
            }                                                                  \
            FMA8(chp, cu0, cu1, cu2, cu3)                                      \
        }

    for (int t = 0; t < TT; t++) {
        const float4* src = (t == 0) ? (const float4*)h0in
                                     : (const float4*)(g_hs + (size_t)(t - 1) * BB * HH);
        float pj, pi, pf, po;

        if (!is_compute) {
            // ---- staging: half 0 (k4 = scol) then half 1 (k4 = scol+64) ----
#pragma unroll
            for (int r = 0; r < 32; r++) {
                int bb = sbb0 + r;
                cp16(&h4[bb * 128 + (scol ^ (bb & 7))], &src[bb * 128 + scol]);
            }
            cp_commit();
#pragma unroll
            for (int r = 0; r < 32; r++) {
                int bb = sbb0 + r;
                int k4 = scol + 64;
                cp16(&h4[bb * 128 + (k4 ^ (bb & 7))], &src[bb * 128 + k4]);
            }
            cp_commit();
            cp_wait<1>();                   // own half-0 group done
        } else {
            // ---- xproj prefetch (DRAM latency hidden under staging) ----
            const float* xp = g_xproj + (size_t)t * GCN * BB;
            pj = xp[((size_t)0 * HH + hq) * BB + B];
            pi = xp[((size_t)1 * HH + hq) * BB + B];
            pf = xp[((size_t)2 * HH + hq) * BB + B];
            po = xp[((size_t)3 * HH + hq) * BB + B];
        }
        __syncthreads();                    // half 0 staged & visible

#pragma unroll
        for (int g = 0; g < 4; g++) { Ae[g] = 0ull; Ao[g] = 0ull; }

        if (is_compute) {
            PIPE_HALF(0)
        } else {
            cp_wait<0>();                   // half 1 done
        }
        __syncthreads();                    // half 1 staged & visible

        if (is_compute) {
            PIPE_HALF(64)

            // gates: j,i,o sigmoid; f tanh (module default quirk)
#pragma unroll
            for (int g = 0; g < 4; g++) add2(Ae[g], Ao[g]);
            float2 vj = unpack2(Ae[0]), vi = unpack2(Ae[1]);
            float2 vf = unpack2(Ae[2]), vo = unpack2(Ae[3]);

            float aj = fsigmoid_(pj + vj.x + vj.y);
            float ai = fsigmoid_(pi + vi.x + vi.y);
            float af = ftanh_(pf + vf.x + vf.y);
            float ao = fsigmoid_(po + vo.x + vo.y);
            c = fmaf(af, c, ai * aj);
            hval = ao * ftanh_(c);
            g_hs[((size_t)t * BB + B) * HH + hq] = hval;
        }

        // ---- grid barrier: red arrival + single-line monotonic poll ----
        __syncthreads();                 // h stores issued block-wide
        const unsigned target = (unsigned)(t + 1) * RBLOCKS;
        if (tid == 0) {
            __threadfence();             // release own h slice
            asm volatile("red.global.add.u32 [%0], %1;"
                         :: "l"(&g_cnt), "r"(1u) : "memory");
            while ((int)(*(volatile unsigned*)&g_cnt - target) < 0) { }
            __threadfence();             // acquire all slices
        }
        __syncthreads();
    }
#undef PIPE_HALF
#undef FMA8

    if (is_compute) {
        size_t OH = (size_t)BB * TT * DD;
        dout[OH + (size_t)B * HH + hq] = hval;
        dout[OH + (size_t)BB * HH + (size_t)B * HH + hq] = c;
    }
}

// =====================================================================
// Kernel 3: y[b][t][d] = sum_h hs[t][b][h] * Wy[h][d] + by[d]
// =====================================================================
__global__ void __launch_bounds__(512) ygemm_kernel(
    const float* __restrict__ Wy, const float* __restrict__ by,
    float* __restrict__ y)
{
    extern __shared__ float sm[];
    float* Wsm = sm;                 // [2][32 kk][256 d]
    float* Hsm = sm + 2 * 32 * 256;  // [2][64 b][40]

    const int t = blockIdx.x;
    const int tid = threadIdx.x;
    const int tb = tid >> 5;
    const int tc = tid & 31;

    ull A[4][4];
#pragma unroll
    for (int j = 0; j < 4; j++)
#pragma unroll
        for (int p = 0; p < 4; p++) A[j][p] = 0ull;

    auto prefetch = [&](int kc, int buf) {
        float* wd = Wsm + buf * (32 * 256);
#pragma unroll
        for (int r = 0; r < 4; r++) {
            int idx = r * 512 + tid;
            int kk = idx >> 6, c4 = idx & 63;
            cp16(wd + kk * 256 + c4 * 4,
                 Wy + (size_t)(kc * 32 + kk) * DD + c4 * 4);
        }
        float* hd = Hsm + buf * (64 * 40);
        {
            int bb = tid >> 3, k4 = tid & 7;
            cp16(hd + bb * 40 + k4 * 4,
                 g_hs + ((size_t)t * BB + bb) * HH + kc * 32 + k4 * 4);
        }
    };

    prefetch(0, 0);
    cp_commit();

    for (int kc = 0; kc < 16; kc++) {
        int buf = kc & 1;
        if (kc < 15) prefetch(kc + 1, buf ^ 1);
        cp_commit();
        cp_wait<1>();
        __syncthreads();

        const float4* Wb4 = (const float4*)(Wsm + buf * (32 * 256));
        const float*  Hb  = Hsm + buf * (64 * 40);
#pragma unroll
        for (int kk4 = 0; kk4 < 8; kk4++) {
            float4 xq[4];
#pragma unroll
            for (int j = 0; j < 4; j++)
                xq[j] = *(const float4*)(Hb + (tb * 4 + j) * 40 + kk4 * 4);
#pragma unroll
            for (int q = 0; q < 4; q++) {
                int kk = kk4 * 4 + q;
                ulonglong2 w0 = *(const ulonglong2*)(Wb4 + kk * 64 + tc);
                ulonglong2 w1 = *(const ulonglong2*)(Wb4 + kk * 64 + 32 + tc);
#pragma unroll
                for (int j = 0; j < 4; j++) {
                    float xs = ((const float*)&xq[j])[q];
                    ull hj = bcast2(xs);
                    fma2(A[j][0], hj, w0.x);
                    fma2(A[j][1], hj, w0.y);
                    fma2(A[j][2], hj, w1.x);
                    fma2(A[j][3], hj, w1.y);
                }
            }
        }
        __syncthreads();
    }

#pragma unroll
    for (int j = 0; j < 4; j++) {
#pragma unroll
        for (int i2 = 0; i2 < 2; i2++) {
            int d = i2 * 128 + tc * 4;
            float2 v0 = unpack2(A[j][i2 * 2 + 0]);
            float2 v1 = unpack2(A[j][i2 * 2 + 1]);
            float4 v = make_float4(v0.x + by[d + 0], v0.y + by[d + 1],
                                   v1.x + by[d + 2], v1.y + by[d + 3]);
            *(float4*)(y + (((size_t)(tb * 4 + j)) * TT + t) * DD + d) = v;
        }
    }
}

// =====================================================================
extern "C" void kernel_launch(void* const* d_in, const int* in_sizes, int n_in,
                              void* d_out, int out_size)
{
    (void)in_sizes; (void)n_in; (void)out_size;
    const float* x  = (const float*)d_in[0];
    const float* h0 = (const float*)d_in[1];
    const float* c0 = (const float*)d_in[2];
    const float* Wj = (const float*)d_in[3];
    const float* Wi = (const float*)d_in[4];
    const float* Wf = (const float*)d_in[5];
    const float* Wo = (const float*)d_in[6];
    const float* Uj = (const float*)d_in[7];
    const float* Ui = (const float*)d_in[8];
    const float* Uf = (const float*)d_in[9];
    const float* Uo = (const float*)d_in[10];
    const float* bj = (const float*)d_in[11];
    const float* bi = (const float*)d_in[12];
    const float* bf = (const float*)d_in[13];
    const float* bo = (const float*)d_in[14];
    const float* Wy = (const float*)d_in[15];
    const float* by = (const float*)d_in[16];
    float* out = (float*)d_out;

    const size_t smem_proj = (size_t)(2 * 32 * 128 + 2 * 64 * 40) * 4;  // 53,248
    const size_t smem_rec  = (size_t)(64 * 512 + 128 * 80) * 4;         // 172,032
    const size_t smem_y    = (size_t)(2 * 32 * 256 + 2 * 64 * 40) * 4;  // 86,016

    cudaFuncSetAttribute(proj_kernel,  cudaFuncAttributeMaxDynamicSharedMemorySize, (int)smem_proj);
    cudaFuncSetAttribute(recur_kernel, cudaFuncAttributeMaxDynamicSharedMemorySize, (int)smem_rec);
    cudaFuncSetAttribute(ygemm_kernel, cudaFuncAttributeMaxDynamicSharedMemorySize, (int)smem_y);

    init_kernel<<<1, 1>>>();
    proj_kernel<<<dim3(16, TT), 256, smem_proj>>>(x, Wj, Wi, Wf, Wo, bj, bi, bf, bo);
    recur_kernel<<<RBLOCKS, 384, smem_rec>>>(h0, c0, Uj, Ui, Uf, Uo, out);
    ygemm_kernel<<<TT, 512, smem_y>>>(Wy, by, out);
}

// round 16
// speedup vs baseline: 1.1201x; 1.1201x over previous
#include <cuda_runtime.h>
#include <cstdint>
#include <cstddef>

#define BB 64
#define TT 2048
#define DD 256
#define HH 512
#define GCN 2048   /* 4*HH gate columns: [j|i|f|o] */
#define RBLOCKS 128

typedef unsigned long long ull;

// ---------------- scratch (device globals: allocation-free rule) ----------------
__device__ float g_xproj[(size_t)TT * GCN * BB];   // [t][gc][b]  (1 GiB)
__device__ float g_hs[(size_t)TT * BB * HH];       // [t][b][h]   (256 MiB)
__device__ unsigned g_cnt;                         // arrival counter (zeroed per launch)

__device__ __forceinline__ float fsigmoid_(float x) {
    return 1.0f / (1.0f + __expf(-x));
}
__device__ __forceinline__ float ftanh_(float x) {
    float e = __expf(2.0f * x);
    return 1.0f - 2.0f / (e + 1.0f);
}

// ---- packed f32x2 helpers (FFMA2 path: only reachable via PTX) ----
__device__ __forceinline__ ull bcast2(float v) {
    ull r;
    asm("mov.b64 %0, {%1, %1};" : "=l"(r) : "r"(__float_as_uint(v)));
    return r;
}
__device__ __forceinline__ void fma2(ull& d, ull a, ull b) {
    asm("fma.rn.f32x2 %0, %1, %2, %0;" : "+l"(d) : "l"(a), "l"(b));
}
__device__ __forceinline__ void add2(ull& d, ull a) {
    asm("add.rn.f32x2 %0, %0, %1;" : "+l"(d) : "l"(a));
}
__device__ __forceinline__ float2 unpack2(ull v) {
    unsigned lo, hi;
    asm("mov.b64 {%0, %1}, %2;" : "=r"(lo), "=r"(hi) : "l"(v));
    return make_float2(__uint_as_float(lo), __uint_as_float(hi));
}

// ---- cp.async helpers ----
__device__ __forceinline__ void cp16(void* dst_smem, const void* src_gmem) {
    unsigned d = (unsigned)__cvta_generic_to_shared(dst_smem);
    asm volatile("cp.async.cg.shared.global [%0], [%1], 16;\n" :: "r"(d), "l"(src_gmem));
}
__device__ __forceinline__ void cp_commit() {
    asm volatile("cp.async.commit_group;\n");
}
template <int N> __device__ __forceinline__ void cp_wait() {
    asm volatile("cp.async.wait_group %0;\n" :: "n"(N));
}

// =====================================================================
// Kernel 0: zero the barrier counter
// =====================================================================
__global__ void init_kernel() {
    g_cnt = 0u;
}

// =====================================================================
// Kernel 1: input projections (double-buffered SGEMM, f32x2 math)
// =====================================================================
__global__ void __launch_bounds__(256) proj_kernel(
    const float* __restrict__ x,
    const float* __restrict__ Wj, const float* __restrict__ Wi,
    const float* __restrict__ Wf, const float* __restrict__ Wo,
    const float* __restrict__ bj, const float* __restrict__ bi,
    const float* __restrict__ bf, const float* __restrict__ bo)
{
    extern __shared__ float sm[];
    float* Wsm = sm;                 // [2][32 kk][128 gc]
    float* Xsm = sm + 2 * 32 * 128;  // [2][64 b][40]

    const int t   = blockIdx.y;
    const int gc0 = blockIdx.x * 128;
    const int g   = gc0 >> 9;
    const int hq0 = gc0 & 511;
    const float* W  = (g == 0) ? Wj : (g == 1) ? Wi : (g == 2) ? Wf : Wo;
    const float* bv = (g == 0) ? bj : (g == 1) ? bi : (g == 2) ? bf : bo;
    const int tid = threadIdx.x;
    const int tb = tid >> 4;
    const int tc = tid & 15;

    ull A[4][4];
#pragma unroll
    for (int j = 0; j < 4; j++)
#pragma unroll
        for (int p = 0; p < 4; p++) A[j][p] = 0ull;

    auto prefetch = [&](int kc, int buf) {
        const float* Wp = W + (size_t)(kc * 32) * HH + hq0;
        float* wd = Wsm + buf * (32 * 128);
#pragma unroll
        for (int r = 0; r < 4; r++) {
            int idx = r * 256 + tid;
            int kk = idx >> 5, c4 = idx & 31;
            cp16(wd + kk * 128 + c4 * 4, Wp + (size_t)kk * HH + c4 * 4);
        }
        float* xd = Xsm + buf * (64 * 40);
#pragma unroll
        for (int r = 0; r < 2; r++) {
            int idx = r * 256 + tid;
            int bb = idx >> 3, k4 = idx & 7;
            cp16(xd + bb * 40 + k4 * 4,
                 x + ((size_t)bb * TT + t) * DD + kc * 32 + k4 * 4);
        }
    };

    prefetch(0, 0);
    cp_commit();

    for (int kc = 0; kc < 8; kc++) {
        int buf = kc & 1;
        if (kc < 7) prefetch(kc + 1, buf ^ 1);
        cp_commit();
        cp_wait<1>();
        __syncthreads();

        const float4* Wb4 = (const float4*)(Wsm + buf * (32 * 128));
        const float*  Xb  = Xsm + buf * (64 * 40);
#pragma unroll
        for (int kk4 = 0; kk4 < 8; kk4++) {
            float4 xq[4];
#pragma unroll
            for (int j = 0; j < 4; j++)
                xq[j] = *(const float4*)(Xb + (tb * 4 + j) * 40 + kk4 * 4);
#pragma unroll
            for (int q = 0; q < 4; q++) {
                int kk = kk4 * 4 + q;
                ulonglong2 w0 = *(const ulonglong2*)(Wb4 + kk * 32 + tc);
                ulonglong2 w1 = *(const ulonglong2*)(Wb4 + kk * 32 + 16 + tc);
#pragma unroll
                for (int j = 0; j < 4; j++) {
                    float xs = ((const float*)&xq[j])[q];
                    ull hj = bcast2(xs);
                    fma2(A[j][0], hj, w0.x);
                    fma2(A[j][1], hj, w0.y);
                    fma2(A[j][2], hj, w1.x);
                    fma2(A[j][3], hj, w1.y);
                }
            }
        }
        __syncthreads();
    }

    float acc[4][8];
#pragma unroll
    for (int j = 0; j < 4; j++)
#pragma unroll
        for (int p = 0; p < 4; p++) {
            float2 v = unpack2(A[j][p]);
            acc[j][p * 2 + 0] = v.x;
            acc[j][p * 2 + 1] = v.y;
        }
#pragma unroll
    for (int i4 = 0; i4 < 2; i4++) {
#pragma unroll
        for (int q = 0; q < 4; q++) {
            int c = i4 * 64 + tc * 4 + q;
            float bb = bv[hq0 + c];
            float4 v = make_float4(acc[0][i4 * 4 + q] + bb, acc[1][i4 * 4 + q] + bb,
                                   acc[2][i4 * 4 + q] + bb, acc[3][i4 * 4 + q] + bb);
            *(float4*)(g_xproj + ((size_t)t * GCN + gc0 + c) * BB + tb * 4) = v;
        }
    }
}

// =====================================================================
// Kernel 2: persistent recurrence. 128 blocks x 256 threads.
// [R13 structure — best known. ONLY change: h stored via smem transpose
// then ONE coalesced STG.128 per batch row by threads 0-63: 64 sector
// writes/block instead of 256, so the pre-barrier fence drains faster.]
// =====================================================================
__global__ void __launch_bounds__(256) recur_kernel(
    const float* __restrict__ h0in, const float* __restrict__ c0in,
    const float* __restrict__ Uj, const float* __restrict__ Ui,
    const float* __restrict__ Uf, const float* __restrict__ Uo,
    float* __restrict__ dout)
{
    extern __shared__ float sm[];
    float* h_smf = sm;               // [64 b][512 k], xor-swizzled float4
    float* U_sm  = sm + 64 * 512;    // [128 k4][4 l][20]: [g][hk0..3] + 4 pad
    float* hbuf  = U_sm + 128 * 80;  // [4 l][72] padded transpose buffer

    const int tid  = threadIdx.x;
    const int bidx = blockIdx.x;
    const int hq_base = bidx * 4;

    // U fill: U_sm[k4*80 + l*20 + g*4 + i] = U_g[(k4*4+i)][hq_base+l]
    for (int idx = tid; idx < 128 * 80; idx += 256) {
        int k4 = idx / 80;
        int r  = idx - k4 * 80;
        int l  = r / 20;
        int s  = r - l * 20;
        float v = 0.0f;
        if (s < 16) {
            int g = s >> 2, i = s & 3;
            const float* Up = (g == 0) ? Uj : (g == 1) ? Ui : (g == 2) ? Uf : Uo;
            v = Up[(size_t)(k4 * 4 + i) * HH + hq_base + l];
        }
        U_sm[idx] = v;
    }
    __syncthreads();

    const bool is_compute = (tid >= 128);
    // staging identity (warps 0-3): thread owns k4-pair (scol, scol+64)
    const int scol = tid & 63;
    const int sbb0 = (tid >> 6) * 32;       // 0 or 32 (within tid<128)
    // compute identity (warps 4-7): 2 (b,hq) pairs per lane
    const int cw   = ((tid - 128) >> 5) & 3;
    const int lane = tid & 31;
    const int l    = lane >> 3;
    const int bq   = lane & 7;
    const int B1   = cw * 8 + bq;           // 0..31
    const int B2   = B1 + 32;
    const int hq   = hq_base + l;

    float4* h4 = (float4*)h_smf;
    const ulonglong2* h2 = (const ulonglong2*)h_smf;
    const float* Ub = U_sm + l * 20;

    float c1 = 0.f, c2 = 0.f, hv1 = 0.f, hv2 = 0.f;
    if (is_compute) {
        c1 = c0in[(size_t)B1 * HH + hq];
        c2 = c0in[(size_t)B2 * HH + hq];
    }

    // 16 chains: [gate][b] x {even,odd} hk partials
    ull Ae[4][2], Ao[4][2];

#define FMA16(HP1, HP2, U0, U1, U2, U3)                                        \
        fma2(Ae[0][0], (HP1).x, (U0).x); fma2(Ao[0][0], (HP1).y, (U0).y);      \
        fma2(Ae[0][1], (HP2).x, (U0).x); fma2(Ao[0][1], (HP2).y, (U0).y);      \
        fma2(Ae[1][0], (HP1).x, (U1).x); fma2(Ao[1][0], (HP1).y, (U1).y);      \
        fma2(Ae[1][1], (HP2).x, (U1).x); fma2(Ao[1][1], (HP2).y, (U1).y);      \
        fma2(Ae[2][0], (HP1).x, (U2).x); fma2(Ao[2][0], (HP1).y, (U2).y);      \
        fma2(Ae[2][1], (HP2).x, (U2).x); fma2(Ao[2][1], (HP2).y, (U2).y);      \
        fma2(Ae[3][0], (HP1).x, (U3).x); fma2(Ao[3][0], (HP1).y, (U3).y);      \
        fma2(Ae[3][1], (HP2).x, (U3).x); fma2(Ao[3][1], (HP2).y, (U3).y);

#define PIPE_HALF(LO)                                                          \
        {                                                                      \
            ulonglong2 chp1 = h2[B1 * 128 + ((LO) ^ bq)];                      \
            ulonglong2 chp2 = h2[B2 * 128 + ((LO) ^ bq)];                      \
            const float* Uc = Ub + (LO) * 80;                                  \
            ulonglong2 cu0 = *(const ulonglong2*)(Uc + 0);                     \
            ulonglong2 cu1 = *(const ulonglong2*)(Uc + 4);                     \
            ulonglong2 cu2 = *(const ulonglong2*)(Uc + 8);                     \
            ulonglong2 cu3 = *(const ulonglong2*)(Uc + 12);                    \
            _Pragma("unroll 7")                                                \
            for (int k4 = (LO); k4 < (LO) + 63; k4++) {                        \
                ulonglong2 nhp1 = h2[B1 * 128 + ((k4 + 1) ^ bq)];              \
                ulonglong2 nhp2 = h2[B2 * 128 + ((k4 + 1) ^ bq)];              \
                const float* Un = Ub + (k4 + 1) * 80;                          \
                ulonglong2 nu0 = *(const ulonglong2*)(Un + 0);                 \
                ulonglong2 nu1 = *(const ulonglong2*)(Un + 4);                 \
                ulonglong2 nu2 = *(const ulonglong2*)(Un + 8);                 \
                ulonglong2 nu3 = *(const ulonglong2*)(Un + 12);                \
                FMA16(chp1, chp2, cu0, cu1, cu2, cu3)                          \
                chp1 = nhp1; chp2 = nhp2;                                      \
                cu0 = nu0; cu1 = nu1; cu2 = nu2; cu3 = nu3;                    \
            }                                                                  \
            FMA16(chp1, chp2, cu0, cu1, cu2, cu3)                              \
        }

    for (int t = 0; t < TT; t++) {
        const float4* src = (t == 0) ? (const float4*)h0in
                                     : (const float4*)(g_hs + (size_t)(t - 1) * BB * HH);
        float pj1, pi1, pf1, po1, pj2, pi2, pf2, po2;

        if (!is_compute) {
            // ---- staging: half 0 (k4 = scol) then half 1 (k4 = scol+64) ----
#pragma unroll
            for (int r = 0; r < 32; r++) {
                int bb = sbb0 + r;
                cp16(&h4[bb * 128 + (scol ^ (bb & 7))], &src[bb * 128 + scol]);
            }
            cp_commit();
#pragma unroll
            for (int r = 0; r < 32; r++) {
                int bb = sbb0 + r;
                int k4 = scol + 64;
                cp16(&h4[bb * 128 + (k4 ^ (bb & 7))], &src[bb * 128 + k4]);
            }
            cp_commit();
            cp_wait<1>();                   // own half-0 group done
        } else {
            // ---- xproj prefetch (DRAM latency hidden under staging+compute) ----
            const float* xp = g_xproj + (size_t)t * GCN * BB;
            pj1 = xp[((size_t)0 * HH + hq) * BB + B1];
            pi1 = xp[((size_t)1 * HH + hq) * BB + B1];
            pf1 = xp[((size_t)2 * HH + hq) * BB + B1];
            po1 = xp[((size_t)3 * HH + hq) * BB + B1];
            pj2 = xp[((size_t)0 * HH + hq) * BB + B2];
            pi2 = xp[((size_t)1 * HH + hq) * BB + B2];
            pf2 = xp[((size_t)2 * HH + hq) * BB + B2];
            po2 = xp[((size_t)3 * HH + hq) * BB + B2];
        }
        __syncthreads();                    // half 0 staged & visible

#pragma unroll
        for (int g = 0; g < 4; g++) {
            Ae[g][0] = Ae[g][1] = 0ull;
            Ao[g][0] = Ao[g][1] = 0ull;
        }

        if (is_compute) {
            PIPE_HALF(0)
        } else {
            cp_wait<0>();                   // half 1 done
        }
        __syncthreads();                    // half 1 staged & visible

        if (is_compute) {
            PIPE_HALF(64)

            // gates: j,i,o sigmoid; f tanh (module default quirk)
#pragma unroll
            for (int g = 0; g < 4; g++) {
                add2(Ae[g][0], Ao[g][0]);
                add2(Ae[g][1], Ao[g][1]);
            }
            float2 vj1 = unpack2(Ae[0][0]), vi1 = unpack2(Ae[1][0]);
            float2 vf1 = unpack2(Ae[2][0]), vo1 = unpack2(Ae[3][0]);
            float2 vj2 = unpack2(Ae[0][1]), vi2 = unpack2(Ae[1][1]);
            float2 vf2 = unpack2(Ae[2][1]), vo2 = unpack2(Ae[3][1]);

            float aj1 = fsigmoid_(pj1 + vj1.x + vj1.y);
            float ai1 = fsigmoid_(pi1 + vi1.x + vi1.y);
            float af1 = ftanh_(pf1 + vf1.x + vf1.y);
            float ao1 = fsigmoid_(po1 + vo1.x + vo1.y);
            c1 = fmaf(af1, c1, ai1 * aj1);
            hv1 = ao1 * ftanh_(c1);

            float aj2 = fsigmoid_(pj2 + vj2.x + vj2.y);
            float ai2 = fsigmoid_(pi2 + vi2.x + vi2.y);
            float af2 = ftanh_(pf2 + vf2.x + vf2.y);
            float ao2 = fsigmoid_(po2 + vo2.x + vo2.y);
            c2 = fmaf(af2, c2, ai2 * aj2);
            hv2 = ao2 * ftanh_(c2);

            // scatter into padded smem transpose buffer (conflict-free)
            hbuf[l * 72 + B1] = hv1;
            hbuf[l * 72 + B2] = hv2;
        }

        // ---- coalesced h store: one STG.128 per batch row ----
        __syncthreads();                 // hbuf writes visible
        if (tid < 64) {
            float4 v = make_float4(hbuf[0 * 72 + tid], hbuf[1 * 72 + tid],
                                   hbuf[2 * 72 + tid], hbuf[3 * 72 + tid]);
            *(float4*)(g_hs + ((size_t)t * BB + tid) * HH + hq_base) = v;
        }

        // ---- grid barrier: red arrival + single-line monotonic poll ----
        __syncthreads();                 // h STG issued block-wide
        const unsigned target = (unsigned)(t + 1) * RBLOCKS;
        if (tid == 0) {
            __threadfence();             // release own h slice
            asm volatile("red.global.add.u32 [%0], %1;"
                         :: "l"(&g_cnt), "r"(1u) : "memory");
            while ((int)(*(volatile unsigned*)&g_cnt - target) < 0) { }
            __threadfence();             // acquire all slices
        }
        __syncthreads();
    }
#undef PIPE_HALF
#undef FMA16

    if (is_compute) {
        size_t OH = (size_t)BB * TT * DD;
        dout[OH + (size_t)B1 * HH + hq] = hv1;
        dout[OH + (size_t)B2 * HH + hq] = hv2;
        dout[OH + (size_t)BB * HH + (size_t)B1 * HH + hq] = c1;
        dout[OH + (size_t)BB * HH + (size_t)B2 * HH + hq] = c2;
    }
}

// =====================================================================
// Kernel 3: y[b][t][d] = sum_h hs[t][b][h] * Wy[h][d] + by[d]
// =====================================================================
__global__ void __launch_bounds__(512) ygemm_kernel(
    const float* __restrict__ Wy, const float* __restrict__ by,
    float* __restrict__ y)
{
    extern __shared__ float sm[];
    float* Wsm = sm;                 // [2][32 kk][256 d]
    float* Hsm = sm + 2 * 32 * 256;  // [2][64 b][40]

    const int t = blockIdx.x;
    const int tid = threadIdx.x;
    const int tb = tid >> 5;
    const int tc = tid & 31;

    ull A[4][4];
#pragma unroll
    for (int j = 0; j < 4; j++)
#pragma unroll
        for (int p = 0; p < 4; p++) A[j][p] = 0ull;

    auto prefetch = [&](int kc, int buf) {
        float* wd = Wsm + buf * (32 * 256);
#pragma unroll
        for (int r = 0; r < 4; r++) {
            int idx = r * 512 + tid;
            int kk = idx >> 6, c4 = idx & 63;
            cp16(wd + kk * 256 + c4 * 4,
                 Wy + (size_t)(kc * 32 + kk) * DD + c4 * 4);
        }
        float* hd = Hsm + buf * (64 * 40);
        {
            int bb = tid >> 3, k4 = tid & 7;
            cp16(hd + bb * 40 + k4 * 4,
                 g_hs + ((size_t)t * BB + bb) * HH + kc * 32 + k4 * 4);
        }
    };

    prefetch(0, 0);
    cp_commit();

    for (int kc = 0; kc < 16; kc++) {
        int buf = kc & 1;
        if (kc < 15) prefetch(kc + 1, buf ^ 1);
        cp_commit();
        cp_wait<1>();
        __syncthreads();

        const float4* Wb4 = (const float4*)(Wsm + buf * (32 * 256));
        const float*  Hb  = Hsm + buf * (64 * 40);
#pragma unroll
        for (int kk4 = 0; kk4 < 8; kk4++) {
            float4 xq[4];
#pragma unroll
            for (int j = 0; j < 4; j++)
                xq[j] = *(const float4*)(Hb + (tb * 4 + j) * 40 + kk4 * 4);
#pragma unroll
            for (int q = 0; q < 4; q++) {
                int kk = kk4 * 4 + q;
                ulonglong2 w0 = *(const ulonglong2*)(Wb4 + kk * 64 + tc);
                ulonglong2 w1 = *(const ulonglong2*)(Wb4 + kk * 64 + 32 + tc);
#pragma unroll
                for (int j = 0; j < 4; j++) {
                    float xs = ((const float*)&xq[j])[q];
                    ull hj = bcast2(xs);
                    fma2(A[j][0], hj, w0.x);
                    fma2(A[j][1], hj, w0.y);
                    fma2(A[j][2], hj, w1.x);
                    fma2(A[j][3], hj, w1.y);
                }
            }
        }
        __syncthreads();
    }

#pragma unroll
    for (int j = 0; j < 4; j++) {
#pragma unroll
        for (int i2 = 0; i2 < 2; i2++) {
            int d = i2 * 128 + tc * 4;
            float2 v0 = unpack2(A[j][i2 * 2 + 0]);
            float2 v1 = unpack2(A[j][i2 * 2 + 1]);
            float4 v = make_float4(v0.x + by[d + 0], v0.y + by[d + 1],
                                   v1.x + by[d + 2], v1.y + by[d + 3]);
            *(float4*)(y + (((size_t)(tb * 4 + j)) * TT + t) * DD + d) = v;
        }
    }
}

// =====================================================================
extern "C" void kernel_launch(void* const* d_in, const int* in_sizes, int n_in,
                              void* d_out, int out_size)
{
    (void)in_sizes; (void)n_in; (void)out_size;
    const float* x  = (const float*)d_in[0];
    const float* h0 = (const float*)d_in[1];
    const float* c0 = (const float*)d_in[2];
    const float* Wj = (const float*)d_in[3];
    const float* Wi = (const float*)d_in[4];
    const float* Wf = (const float*)d_in[5];
    const float* Wo = (const float*)d_in[6];
    const float* Uj = (const float*)d_in[7];
    const float* Ui = (const float*)d_in[8];
    const float* Uf = (const float*)d_in[9];
    const float* Uo = (const float*)d_in[10];
    const float* bj = (const float*)d_in[11];
    const float* bi = (const float*)d_in[12];
    const float* bf = (const float*)d_in[13];
    const float* bo = (const float*)d_in[14];
    const float* Wy = (const float*)d_in[15];
    const float* by = (const float*)d_in[16];
    float* out = (float*)d_out;

    const size_t smem_proj = (size_t)(2 * 32 * 128 + 2 * 64 * 40) * 4;        // 53,248
    const size_t smem_rec  = (size_t)(64 * 512 + 128 * 80 + 4 * 72) * 4;      // 173,184
    const size_t smem_y    = (size_t)(2 * 32 * 256 + 2 * 64 * 40) * 4;        // 86,016

    cudaFuncSetAttribute(proj_kernel,  cudaFuncAttributeMaxDynamicSharedMemorySize, (int)smem_proj);
    cudaFuncSetAttribute(recur_kernel, cudaFuncAttributeMaxDynamicSharedMemorySize, (int)smem_rec);
    cudaFuncSetAttribute(ygemm_kernel, cudaFuncAttributeMaxDynamicSharedMemorySize, (int)smem_y);

    init_kernel<<<1, 1>>>();
    proj_kernel<<<dim3(16, TT), 256, smem_proj>>>(x, Wj, Wi, Wf, Wo, bj, bi, bf, bo);
    recur_kernel<<<RBLOCKS, 256, smem_rec>>>(h0, c0, Uj, Ui, Uf, Uo, out);
    ygemm_kernel<<<TT, 512, smem_y>>>(Wy, by, out);
}

// round 17
// speedup vs baseline: 1.1227x; 1.0023x over previous
#include <cuda_runtime.h>
#include <cstdint>
#include <cstddef>

#define BB 64
#define TT 2048
#define DD 256
#define HH 512
#define GCN 2048   /* 4*HH gate columns: [j|i|f|o] */
#define RBLOCKS 128

typedef unsigned long long ull;

// ---------------- scratch (device globals: allocation-free rule) ----------------
__device__ float g_xproj[(size_t)TT * GCN * BB];   // [t][gc][b]  (1 GiB)
__device__ float g_hs[(size_t)TT * BB * HH];       // [t][b][h]   (256 MiB)
__device__ unsigned g_cnt;                         // recur barrier counter
__device__ unsigned g_tdone[TT];                   // proj progress: 16 blocks per t

__device__ __forceinline__ float fsigmoid_(float x) {
    return 1.0f / (1.0f + __expf(-x));
}
__device__ __forceinline__ float ftanh_(float x) {
    float e = __expf(2.0f * x);
    return 1.0f - 2.0f / (e + 1.0f);
}

// ---- packed f32x2 helpers (FFMA2 path: only reachable via PTX) ----
__device__ __forceinline__ ull bcast2(float v) {
    ull r;
    asm("mov.b64 %0, {%1, %1};" : "=l"(r) : "r"(__float_as_uint(v)));
    return r;
}
__device__ __forceinline__ void fma2(ull& d, ull a, ull b) {
    asm("fma.rn.f32x2 %0, %1, %2, %0;" : "+l"(d) : "l"(a), "l"(b));
}
__device__ __forceinline__ void add2(ull& d, ull a) {
    asm("add.rn.f32x2 %0, %0, %1;" : "+l"(d) : "l"(a));
}
__device__ __forceinline__ float2 unpack2(ull v) {
    unsigned lo, hi;
    asm("mov.b64 {%0, %1}, %2;" : "=r"(lo), "=r"(hi) : "l"(v));
    return make_float2(__uint_as_float(lo), __uint_as_float(hi));
}

// ---- cp.async helpers ----
__device__ __forceinline__ void cp16(void* dst_smem, const void* src_gmem) {
    unsigned d = (unsigned)__cvta_generic_to_shared(dst_smem);
    asm volatile("cp.async.cg.shared.global [%0], [%1], 16;\n" :: "r"(d), "l"(src_gmem));
}
__device__ __forceinline__ void cp_commit() {
    asm volatile("cp.async.commit_group;\n");
}
template <int N> __device__ __forceinline__ void cp_wait() {
    asm volatile("cp.async.wait_group %0;\n" :: "n"(N));
}

// =====================================================================
// Kernel 0: zero the barrier counter + proj progress counters
// =====================================================================
__global__ void __launch_bounds__(256) init_kernel() {
    int tid = threadIdx.x;
    if (tid == 0) g_cnt = 0u;
    for (int i = tid; i < TT; i += 256) g_tdone[i] = 0u;
}

// =====================================================================
// Kernel 1: input projections (double-buffered SGEMM, f32x2 math).
// Runs CONCURRENTLY with recur (2nd stream): signals per-t completion
// via g_tdone[t] (16 blocks per t).
// =====================================================================
__global__ void __launch_bounds__(256) proj_kernel(
    const float* __restrict__ x,
    const float* __restrict__ Wj, const float* __restrict__ Wi,
    const float* __restrict__ Wf, const float* __restrict__ Wo,
    const float* __restrict__ bj, const float* __restrict__ bi,
    const float* __restrict__ bf, const float* __restrict__ bo)
{
    extern __shared__ float sm[];
    float* Wsm = sm;                 // [2][32 kk][128 gc]
    float* Xsm = sm + 2 * 32 * 128;  // [2][64 b][40]

    const int t   = blockIdx.y;
    const int gc0 = blockIdx.x * 128;
    const int g   = gc0 >> 9;
    const int hq0 = gc0 & 511;
    const float* W  = (g == 0) ? Wj : (g == 1) ? Wi : (g == 2) ? Wf : Wo;
    const float* bv = (g == 0) ? bj : (g == 1) ? bi : (g == 2) ? bf : bo;
    const int tid = threadIdx.x;
    const int tb = tid >> 4;
    const int tc = tid & 15;

    ull A[4][4];
#pragma unroll
    for (int j = 0; j < 4; j++)
#pragma unroll
        for (int p = 0; p < 4; p++) A[j][p] = 0ull;

    auto prefetch = [&](int kc, int buf) {
        const float* Wp = W + (size_t)(kc * 32) * HH + hq0;
        float* wd = Wsm + buf * (32 * 128);
#pragma unroll
        for (int r = 0; r < 4; r++) {
            int idx = r * 256 + tid;
            int kk = idx >> 5, c4 = idx & 31;
            cp16(wd + kk * 128 + c4 * 4, Wp + (size_t)kk * HH + c4 * 4);
        }
        float* xd = Xsm + buf * (64 * 40);
#pragma unroll
        for (int r = 0; r < 2; r++) {
            int idx = r * 256 + tid;
            int bb = idx >> 3, k4 = idx & 7;
            cp16(xd + bb * 40 + k4 * 4,
                 x + ((size_t)bb * TT + t) * DD + kc * 32 + k4 * 4);
        }
    };

    prefetch(0, 0);
    cp_commit();

    for (int kc = 0; kc < 8; kc++) {
        int buf = kc & 1;
        if (kc < 7) prefetch(kc + 1, buf ^ 1);
        cp_commit();
        cp_wait<1>();
        __syncthreads();

        const float4* Wb4 = (const float4*)(Wsm + buf * (32 * 128));
        const float*  Xb  = Xsm + buf * (64 * 40);
#pragma unroll
        for (int kk4 = 0; kk4 < 8; kk4++) {
            float4 xq[4];
#pragma unroll
            for (int j = 0; j < 4; j++)
                xq[j] = *(const float4*)(Xb + (tb * 4 + j) * 40 + kk4 * 4);
#pragma unroll
            for (int q = 0; q < 4; q++) {
                int kk = kk4 * 4 + q;
                ulonglong2 w0 = *(const ulonglong2*)(Wb4 + kk * 32 + tc);
                ulonglong2 w1 = *(const ulonglong2*)(Wb4 + kk * 32 + 16 + tc);
#pragma unroll
                for (int j = 0; j < 4; j++) {
                    float xs = ((const float*)&xq[j])[q];
                    ull hj = bcast2(xs);
                    fma2(A[j][0], hj, w0.x);
                    fma2(A[j][1], hj, w0.y);
                    fma2(A[j][2], hj, w1.x);
                    fma2(A[j][3], hj, w1.y);
                }
            }
        }
        __syncthreads();
    }

    float acc[4][8];
#pragma unroll
    for (int j = 0; j < 4; j++)
#pragma unroll
        for (int p = 0; p < 4; p++) {
            float2 v = unpack2(A[j][p]);
            acc[j][p * 2 + 0] = v.x;
            acc[j][p * 2 + 1] = v.y;
        }
#pragma unroll
    for (int i4 = 0; i4 < 2; i4++) {
#pragma unroll
        for (int q = 0; q < 4; q++) {
            int c = i4 * 64 + tc * 4 + q;
            float bb = bv[hq0 + c];
            float4 v = make_float4(acc[0][i4 * 4 + q] + bb, acc[1][i4 * 4 + q] + bb,
                                   acc[2][i4 * 4 + q] + bb, acc[3][i4 * 4 + q] + bb);
            *(float4*)(g_xproj + ((size_t)t * GCN + gc0 + c) * BB + tb * 4) = v;
        }
    }

    // ---- progress signal: release stores, then one arrival for this t ----
    __syncthreads();
    if (tid == 0) {
        __threadfence();
        asm volatile("red.global.add.u32 [%0], %1;"
                     :: "l"(&g_tdone[t]), "r"(1u) : "memory");
    }
}

// =====================================================================
// Kernel 2: persistent recurrence. 128 blocks x 256 threads.
// [R16 structure — best known. ONLY change: compute warps gate their
// xproj[t] prefetch on g_tdone[t] == 16 (proj runs concurrently).]
// =====================================================================
__global__ void __launch_bounds__(256) recur_kernel(
    const float* __restrict__ h0in, const float* __restrict__ c0in,
    const float* __restrict__ Uj, const float* __restrict__ Ui,
    const float* __restrict__ Uf, const float* __restrict__ Uo,
    float* __restrict__ dout)
{
    extern __shared__ float sm[];
    float* h_smf = sm;               // [64 b][512 k], xor-swizzled float4
    float* U_sm  = sm + 64 * 512;    // [128 k4][4 l][20]: [g][hk0..3] + 4 pad
    float* hbuf  = U_sm + 128 * 80;  // [4 l][72] padded transpose buffer

    const int tid  = threadIdx.x;
    const int bidx = blockIdx.x;
    const int hq_base = bidx * 4;

    // U fill: U_sm[k4*80 + l*20 + g*4 + i] = U_g[(k4*4+i)][hq_base+l]
    for (int idx = tid; idx < 128 * 80; idx += 256) {
        int k4 = idx / 80;
        int r  = idx - k4 * 80;
        int l  = r / 20;
        int s  = r - l * 20;
        float v = 0.0f;
        if (s < 16) {
            int g = s >> 2, i = s & 3;
            const float* Up = (g == 0) ? Uj : (g == 1) ? Ui : (g == 2) ? Uf : Uo;
            v = Up[(size_t)(k4 * 4 + i) * HH + hq_base + l];
        }
        U_sm[idx] = v;
    }
    __syncthreads();

    const bool is_compute = (tid >= 128);
    // staging identity (warps 0-3): thread owns k4-pair (scol, scol+64)
    const int scol = tid & 63;
    const int sbb0 = (tid >> 6) * 32;       // 0 or 32 (within tid<128)
    // compute identity (warps 4-7): 2 (b,hq) pairs per lane
    const int cw   = ((tid - 128) >> 5) & 3;
    const int lane = tid & 31;
    const int l    = lane >> 3;
    const int bq   = lane & 7;
    const int B1   = cw * 8 + bq;           // 0..31
    const int B2   = B1 + 32;
    const int hq   = hq_base + l;

    float4* h4 = (float4*)h_smf;
    const ulonglong2* h2 = (const ulonglong2*)h_smf;
    const float* Ub = U_sm + l * 20;

    float c1 = 0.f, c2 = 0.f, hv1 = 0.f, hv2 = 0.f;
    if (is_compute) {
        c1 = c0in[(size_t)B1 * HH + hq];
        c2 = c0in[(size_t)B2 * HH + hq];
    }

    // 16 chains: [gate][b] x {even,odd} hk partials
    ull Ae[4][2], Ao[4][2];

#define FMA16(HP1, HP2, U0, U1, U2, U3)                                        \
        fma2(Ae[0][0], (HP1).x, (U0).x); fma2(Ao[0][0], (HP1).y, (U0).y);      \
        fma2(Ae[0][1], (HP2).x, (U0).x); fma2(Ao[0][1], (HP2).y, (U0).y);      \
        fma2(Ae[1][0], (HP1).x, (U1).x); fma2(Ao[1][0], (HP1).y, (U1).y);      \
        fma2(Ae[1][1], (HP2).x, (U1).x); fma2(Ao[1][1], (HP2).y, (U1).y);      \
        fma2(Ae[2][0], (HP1).x, (U2).x); fma2(Ao[2][0], (HP1).y, (U2).y);      \
        fma2(Ae[2][1], (HP2).x, (U2).x); fma2(Ao[2][1], (HP2).y, (U2).y);      \
        fma2(Ae[3][0], (HP1).x, (U3).x); fma2(Ao[3][0], (HP1).y, (U3).y);      \
        fma2(Ae[3][1], (HP2).x, (U3).x); fma2(Ao[3][1], (HP2).y, (U3).y);

#define PIPE_HALF(LO)                                                          \
        {                                                                      \
            ulonglong2 chp1 = h2[B1 * 128 + ((LO) ^ bq)];                      \
            ulonglong2 chp2 = h2[B2 * 128 + ((LO) ^ bq)];                      \
            const float* Uc = Ub + (LO) * 80;                                  \
            ulonglong2 cu0 = *(const ulonglong2*)(Uc + 0);                     \
            ulonglong2 cu1 = *(const ulonglong2*)(Uc + 4);                     \
            ulonglong2 cu2 = *(const ulonglong2*)(Uc + 8);                     \
            ulonglong2 cu3 = *(const ulonglong2*)(Uc + 12);                    \
            _Pragma("unroll 7")                                                \
            for (int k4 = (LO); k4 < (LO) + 63; k4++) {                        \
                ulonglong2 nhp1 = h2[B1 * 128 + ((k4 + 1) ^ bq)];              \
                ulonglong2 nhp2 = h2[B2 * 128 + ((k4 + 1) ^ bq)];              \
                const float* Un = Ub + (k4 + 1) * 80;                          \
                ulonglong2 nu0 = *(const ulonglong2*)(Un + 0);                 \
                ulonglong2 nu1 = *(const ulonglong2*)(Un + 4);                 \
                ulonglong2 nu2 = *(const ulonglong2*)(Un + 8);                 \
                ulonglong2 nu3 = *(const ulonglong2*)(Un + 12);                \
                FMA16(chp1, chp2, cu0, cu1, cu2, cu3)                          \
                chp1 = nhp1; chp2 = nhp2;                                      \
                cu0 = nu0; cu1 = nu1; cu2 = nu2; cu3 = nu3;                    \
            }                                                                  \
            FMA16(chp1, chp2, cu0, cu1, cu2, cu3)                              \
        }

    for (int t = 0; t < TT; t++) {
        const float4* src = (t == 0) ? (const float4*)h0in
                                     : (const float4*)(g_hs + (size_t)(t - 1) * BB * HH);
        float pj1, pi1, pf1, po1, pj2, pi2, pf2, po2;

        if (!is_compute) {
            // ---- staging: half 0 (k4 = scol) then half 1 (k4 = scol+64) ----
#pragma unroll
            for (int r = 0; r < 32; r++) {
                int bb = sbb0 + r;
                cp16(&h4[bb * 128 + (scol ^ (bb & 7))], &src[bb * 128 + scol]);
            }
            cp_commit();
#pragma unroll
            for (int r = 0; r < 32; r++) {
                int bb = sbb0 + r;
                int k4 = scol + 64;
                cp16(&h4[bb * 128 + (k4 ^ (bb & 7))], &src[bb * 128 + k4]);
            }
            cp_commit();
            cp_wait<1>();                   // own half-0 group done
        } else {
            // ---- gate on proj progress for this t (overlaps staging) ----
            if (lane == 0) {
                while ((int)(*(volatile unsigned*)&g_tdone[t] - 16u) < 0) { }
            }
            __syncwarp();
            // ---- xproj prefetch (DRAM latency hidden under staging) ----
            const float* xp = g_xproj + (size_t)t * GCN * BB;
            pj1 = xp[((size_t)0 * HH + hq) * BB + B1];
            pi1 = xp[((size_t)1 * HH + hq) * BB + B1];
            pf1 = xp[((size_t)2 * HH + hq) * BB + B1];
            po1 = xp[((size_t)3 * HH + hq) * BB + B1];
            pj2 = xp[((size_t)0 * HH + hq) * BB + B2];
            pi2 = xp[((size_t)1 * HH + hq) * BB + B2];
            pf2 = xp[((size_t)2 * HH + hq) * BB + B2];
            po2 = xp[((size_t)3 * HH + hq) * BB + B2];
        }
        __syncthreads();                    // half 0 staged & visible

#pragma unroll
        for (int g = 0; g < 4; g++) {
            Ae[g][0] = Ae[g][1] = 0ull;
            Ao[g][0] = Ao[g][1] = 0ull;
        }

        if (is_compute) {
            PIPE_HALF(0)
        } else {
            cp_wait<0>();                   // half 1 done
        }
        __syncthreads();                    // half 1 staged & visible

        if (is_compute) {
            PIPE_HALF(64)

            // gates: j,i,o sigmoid; f tanh (module default quirk)
#pragma unroll
            for (int g = 0; g < 4; g++) {
                add2(Ae[g][0], Ao[g][0]);
                add2(Ae[g][1], Ao[g][1]);
            }
            float2 vj1 = unpack2(Ae[0][0]), vi1 = unpack2(Ae[1][0]);
            float2 vf1 = unpack2(Ae[2][0]), vo1 = unpack2(Ae[3][0]);
            float2 vj2 = unpack2(Ae[0][1]), vi2 = unpack2(Ae[1][1]);
            float2 vf2 = unpack2(Ae[2][1]), vo2 = unpack2(Ae[3][1]);

            float aj1 = fsigmoid_(pj1 + vj1.x + vj1.y);
            float ai1 = fsigmoid_(pi1 + vi1.x + vi1.y);
            float af1 = ftanh_(pf1 + vf1.x + vf1.y);
            float ao1 = fsigmoid_(po1 + vo1.x + vo1.y);
            c1 = fmaf(af1, c1, ai1 * aj1);
            hv1 = ao1 * ftanh_(c1);

            float aj2 = fsigmoid_(pj2 + vj2.x + vj2.y);
            float ai2 = fsigmoid_(pi2 + vi2.x + vi2.y);
            float af2 = ftanh_(pf2 + vf2.x + vf2.y);
            float ao2 = fsigmoid_(po2 + vo2.x + vo2.y);
            c2 = fmaf(af2, c2, ai2 * aj2);
            hv2 = ao2 * ftanh_(c2);

            // scatter into padded smem transpose buffer (conflict-free)
            hbuf[l * 72 + B1] = hv1;
            hbuf[l * 72 + B2] = hv2;
        }

        // ---- coalesced h store: one STG.128 per batch row ----
        __syncthreads();                 // hbuf writes visible
        if (tid < 64) {
            float4 v = make_float4(hbuf[0 * 72 + tid], hbuf[1 * 72 + tid],
                                   hbuf[2 * 72 + tid], hbuf[3 * 72 + tid]);
            *(float4*)(g_hs + ((size_t)t * BB + tid) * HH + hq_base) = v;
        }

        // ---- grid barrier: red arrival + single-line monotonic poll ----
        __syncthreads();                 // h STG issued block-wide
        const unsigned target = (unsigned)(t + 1) * RBLOCKS;
        if (tid == 0) {
            __threadfence();             // release own h slice
            asm volatile("red.global.add.u32 [%0], %1;"
                         :: "l"(&g_cnt), "r"(1u) : "memory");
            while ((int)(*(volatile unsigned*)&g_cnt - target) < 0) { }
            __threadfence();             // acquire all slices
        }
        __syncthreads();
    }
#undef PIPE_HALF
#undef FMA16

    if (is_compute) {
        size_t OH = (size_t)BB * TT * DD;
        dout[OH + (size_t)B1 * HH + hq] = hv1;
        dout[OH + (size_t)B2 * HH + hq] = hv2;
        dout[OH + (size_t)BB * HH + (size_t)B1 * HH + hq] = c1;
        dout[OH + (size_t)BB * HH + (size_t)B2 * HH + hq] = c2;
    }
}

// =====================================================================
// Kernel 3: y[b][t][d] = sum_h hs[t][b][h] * Wy[h][d] + by[d]
// =====================================================================
__global__ void __launch_bounds__(512) ygemm_kernel(
    const float* __restrict__ Wy, const float* __restrict__ by,
    float* __restrict__ y)
{
    extern __shared__ float sm[];
    float* Wsm = sm;                 // [2][32 kk][256 d]
    float* Hsm = sm + 2 * 32 * 256;  // [2][64 b][40]

    const int t = blockIdx.x;
    const int tid = threadIdx.x;
    const int tb = tid >> 5;
    const int tc = tid & 31;

    ull A[4][4];
#pragma unroll
    for (int j = 0; j < 4; j++)
#pragma unroll
        for (int p = 0; p < 4; p++) A[j][p] = 0ull;

    auto prefetch = [&](int kc, int buf) {
        float* wd = Wsm + buf * (32 * 256);
#pragma unroll
        for (int r = 0; r < 4; r++) {
            int idx = r * 512 + tid;
            int kk = idx >> 6, c4 = idx & 63;
            cp16(wd + kk * 256 + c4 * 4,
                 Wy + (size_t)(kc * 32 + kk) * DD + c4 * 4);
        }
        float* hd = Hsm + buf * (64 * 40);
        {
            int bb = tid >> 3, k4 = tid & 7;
            cp16(hd + bb * 40 + k4 * 4,
                 g_hs + ((size_t)t * BB + bb) * HH + kc * 32 + k4 * 4);
        }
    };

    prefetch(0, 0);
    cp_commit();

    for (int kc = 0; kc < 16; kc++) {
        int buf = kc & 1;
        if (kc < 15) prefetch(kc + 1, buf ^ 1);
        cp_commit();
        cp_wait<1>();
        __syncthreads();

        const float4* Wb4 = (const float4*)(Wsm + buf * (32 * 256));
        const float*  Hb  = Hsm + buf * (64 * 40);
#pragma unroll
        for (int kk4 = 0; kk4 < 8; kk4++) {
            float4 xq[4];
#pragma unroll
            for (int j = 0; j < 4; j++)
                xq[j] = *(const float4*)(Hb + (tb * 4 + j) * 40 + kk4 * 4);
#pragma unroll
            for (int q = 0; q < 4; q++) {
                int kk = kk4 * 4 + q;
                ulonglong2 w0 = *(const ulonglong2*)(Wb4 + kk * 64 + tc);
                ulonglong2 w1 = *(const ulonglong2*)(Wb4 + kk * 64 + 32 + tc);
#pragma unroll
                for (int j = 0; j < 4; j++) {
                    float xs = ((const float*)&xq[j])[q];
                    ull hj = bcast2(xs);
                    fma2(A[j][0], hj, w0.x);
                    fma2(A[j][1], hj, w0.y);
                    fma2(A[j][2], hj, w1.x);
                    fma2(A[j][3], hj, w1.y);
                }
            }
        }
        __syncthreads();
    }

#pragma unroll
    for (int j = 0; j < 4; j++) {
#pragma unroll
        for (int i2 = 0; i2 < 2; i2++) {
            int d = i2 * 128 + tc * 4;
            float2 v0 = unpack2(A[j][i2 * 2 + 0]);
            float2 v1 = unpack2(A[j][i2 * 2 + 1]);
            float4 v = make_float4(v0.x + by[d + 0], v0.y + by[d + 1],
                                   v1.x + by[d + 2], v1.y + by[d + 3]);
            *(float4*)(y + (((size_t)(tb * 4 + j)) * TT + t) * DD + d) = v;
        }
    }
}

// =====================================================================
extern "C" void kernel_launch(void* const* d_in, const int* in_sizes, int n_in,
                              void* d_out, int out_size)
{
    (void)in_sizes; (void)n_in; (void)out_size;
    const float* x  = (const float*)d_in[0];
    const float* h0 = (const float*)d_in[1];
    const float* c0 = (const float*)d_in[2];
    const float* Wj = (const float*)d_in[3];
    const float* Wi = (const float*)d_in[4];
    const float* Wf = (const float*)d_in[5];
    const float* Wo = (const float*)d_in[6];
    const float* Uj = (const float*)d_in[7];
    const float* Ui = (const float*)d_in[8];
    const float* Uf = (const float*)d_in[9];
    const float* Uo = (const float*)d_in[10];
    const float* bj = (const float*)d_in[11];
    const float* bi = (const float*)d_in[12];
    const float* bf = (const float*)d_in[13];
    const float* bo = (const float*)d_in[14];
    const float* Wy = (const float*)d_in[15];
    const float* by = (const float*)d_in[16];
    float* out = (float*)d_out;

    const size_t smem_proj = (size_t)(2 * 32 * 128 + 2 * 64 * 40) * 4;        // 53,248
    const size_t smem_rec  = (size_t)(64 * 512 + 128 * 80 + 4 * 72) * 4;      // 173,184
    const size_t smem_y    = (size_t)(2 * 32 * 256 + 2 * 64 * 40) * 4;        // 86,016

    cudaFuncSetAttribute(proj_kernel,  cudaFuncAttributeMaxDynamicSharedMemorySize, (int)smem_proj);
    cudaFuncSetAttribute(recur_kernel, cudaFuncAttributeMaxDynamicSharedMemorySize, (int)smem_rec);
    cudaFuncSetAttribute(ygemm_kernel, cudaFuncAttributeMaxDynamicSharedMemorySize, (int)smem_y);

    // ---- multi-stream fork: proj runs concurrently with recur ----
    cudaStream_t s2;
    cudaStreamCreate(&s2);
    cudaEvent_t e1, e2;
    cudaEventCreateWithFlags(&e1, cudaEventDisableTiming);
    cudaEventCreateWithFlags(&e2, cudaEventDisableTiming);

    init_kernel<<<1, 256>>>();
    cudaEventRecord(e1, 0);
    cudaStreamWaitEvent(s2, e1, 0);
    proj_kernel<<<dim3(16, TT), 256, smem_proj, s2>>>(x, Wj, Wi, Wf, Wo, bj, bi, bf, bo);
    cudaEventRecord(e2, s2);

    recur_kernel<<<RBLOCKS, 256, smem_rec>>>(h0, c0, Uj, Ui, Uf, Uo, out);

    cudaStreamWaitEvent(0, e2, 0);   // join proj branch before ygemm
    ygemm_kernel<<<TT, 512, smem_y>>>(Wy, by, out);

    cudaEventDestroy(e1);
    cudaEventDestroy(e2);
    cudaStreamDestroy(s2);
}